// round 3
// baseline (speedup 1.0000x reference)
#include <cuda_runtime.h>

#define T_STEPS 512
#define NBATCH  64
#define IDIM    512
#define HDIM    512
#define G4H     2048
#define NBLOCKS 128

// Scratch (allocation-free rule: __device__ globals)
__device__ float    g_xp[(size_t)T_STEPS * NBATCH * G4H];   // [T,B,4H] input projections
__device__ float    g_hbuf[2][HDIM * NBATCH];               // ping-pong h, layout [h][b]
__device__ unsigned g_count;                                 // barrier arrival counter
__device__ unsigned g_gen;                                   // barrier generation

// ---------------------------------------------------------------------------
// Kernel 1: x_proj[M=T*B, N=4H] = x[M,K] @ W_ih[N,K]^T + (b_ih + b_hh)
// 128x128 block tile, 8x8 per-thread tile, BK=16, 256 threads.
// ---------------------------------------------------------------------------
#define BM 128
#define BN 128
#define BK 16

__global__ __launch_bounds__(256, 2)
void xproj_gemm(const float* __restrict__ x, const float* __restrict__ Wih,
                const float* __restrict__ bih, const float* __restrict__ bhh) {
    __shared__ float As[BK][BM + 4];
    __shared__ float Bs[BK][BN + 4];
    const int tid = threadIdx.x;
    const int mb = blockIdx.y, nb = blockIdx.x;
    const float* Ap = x   + (size_t)mb * BM * IDIM;
    const float* Bp = Wih + (size_t)nb * BN * IDIM;
    const int tr = tid >> 4, tc = tid & 15;   // 16x16 thread grid

    float acc[8][8];
#pragma unroll
    for (int i = 0; i < 8; i++)
#pragma unroll
        for (int j = 0; j < 8; j++) acc[i][j] = 0.f;

    for (int k0 = 0; k0 < IDIM; k0 += BK) {
#pragma unroll
        for (int i = 0; i < 2; i++) {
            int lid = tid + i * 256;         // 0..511
            int row = lid >> 2, kq = lid & 3;
            float4 v = *(const float4*)(Ap + (size_t)row * IDIM + k0 + kq * 4);
            As[kq*4+0][row] = v.x; As[kq*4+1][row] = v.y;
            As[kq*4+2][row] = v.z; As[kq*4+3][row] = v.w;
            float4 w = *(const float4*)(Bp + (size_t)row * IDIM + k0 + kq * 4);
            Bs[kq*4+0][row] = w.x; Bs[kq*4+1][row] = w.y;
            Bs[kq*4+2][row] = w.z; Bs[kq*4+3][row] = w.w;
        }
        __syncthreads();
#pragma unroll
        for (int k = 0; k < BK; k++) {
            float a[8], b[8];
            *(float4*)&a[0] = *(const float4*)&As[k][tr * 4];
            *(float4*)&a[4] = *(const float4*)&As[k][64 + tr * 4];
            *(float4*)&b[0] = *(const float4*)&Bs[k][tc * 4];
            *(float4*)&b[4] = *(const float4*)&Bs[k][64 + tc * 4];
#pragma unroll
            for (int i = 0; i < 8; i++)
#pragma unroll
                for (int j = 0; j < 8; j++) acc[i][j] += a[i] * b[j];
        }
        __syncthreads();
    }

#pragma unroll
    for (int i = 0; i < 8; i++) {
        int m = mb * BM + ((i < 4) ? tr * 4 + i : 64 + tr * 4 + (i - 4));
#pragma unroll
        for (int j = 0; j < 8; j++) {
            int n = nb * BN + ((j < 4) ? tc * 4 + j : 64 + tc * 4 + (j - 4));
            g_xp[(size_t)m * G4H + n] = acc[i][j] + bih[n] + bhh[n];
        }
    }
}

// ---------------------------------------------------------------------------
// Grid barrier: sense-reversing, resident-grid spin. g_count returns to 0 at
// every release; g_gen only compared for equality (wrap-safe across replays).
// ---------------------------------------------------------------------------
__device__ __forceinline__ void grid_barrier() {
    __threadfence();       // each thread's stores visible before arrival
    __syncthreads();       // all threads fenced before thread0 arrives
    if (threadIdx.x == 0) {
        volatile unsigned* vgen = &g_gen;
        unsigned gen = *vgen;
        if (atomicAdd(&g_count, 1u) == NBLOCKS - 1u) {
            g_count = 0u;
            __threadfence();
            atomicAdd(&g_gen, 1u);
        } else {
            while (*vgen == gen) { __nanosleep(64); }
        }
    }
    __syncthreads();
}

// ---------------------------------------------------------------------------
// Kernel 2: persistent recurrence. 128 blocks = 64 col-groups x 2 batch-groups.
// Block owns 8 h-columns, 32 batches. Per step:
//   gates[32b,32r] = h[32b,512] @ Whh_sub[32r,512]^T  (+x_proj), r = gate*8+col
// 256 thr = 4 k-groups(K=128) x 64 tile-threads (4b x 4r register tiles).
// SMEM: w 64KB (persistent) + h 64KB (per step) + partials 16KB + c 1KB.
// ---------------------------------------------------------------------------
#define COLS 8
#define BB   32

extern __shared__ float smem[];

__global__ __launch_bounds__(256, 1)
void lstm_rec(const float* __restrict__ Whh, float* __restrict__ out) {
    float* w_sh = smem;            // [512][32]  w_sh[k*32 + r]
    float* h_sh = smem + 16384;    // [512][32]  h_sh[k*32 + b]
    float* part = smem + 32768;    // [4][32][32]
    float* c_sh = smem + 36864;    // [32][8]
    const int tid = threadIdx.x;
    const int colbase = blockIdx.x * COLS;
    const int bbase   = blockIdx.y * BB;

    // Load this block's W_hh slice (once per launch). r = gate*8 + col.
    for (int idx = tid; idx < 32 * 512; idx += 256) {
        int r = idx >> 9, k = idx & 511;
        int g = r >> 3, c = r & 7;
        w_sh[k * 32 + r] = Whh[((size_t)(g * HDIM + colbase + c)) * HDIM + k];
    }
    // Init c = 0 and zero our slice of h buffer 0
    c_sh[tid] = 0.f;
    {
        int c = tid >> 5, b = tid & 31;
        g_hbuf[0][(colbase + c) * NBATCH + bbase + b] = 0.f;
    }
    grid_barrier();

    const int kg = tid >> 6;            // 0..3
    const int tt = tid & 63;
    const int bx = tt & 7;              // batch group (4 batches)
    const int rx = tt >> 3;             // row group (4 rows)
    const int b_ep  = tid >> 3;         // epilogue: batch 0..31
    const int c_ep  = tid & 7;          // epilogue: col 0..7

    for (int t = 0; t < T_STEPS; t++) {
        const int cur = t & 1;
        // Load h (written by other SMs) — MUST bypass L1 (__ldcg)
        {
            const float4* src = (const float4*)&g_hbuf[cur][0];
            for (int q = tid; q < 4096; q += 256) {
                int k = q >> 3, b4 = q & 7;
                float4 v = __ldcg((const float4*)&g_hbuf[cur][k * NBATCH + bbase + b4 * 4]);
                ((float4*)h_sh)[q] = v;
            }
            (void)src;
        }
        __syncthreads();

        // Micro-GEMM: acc[4b][4r] over K slice [kg*128, kg*128+128)
        float acc[4][4];
#pragma unroll
        for (int i = 0; i < 4; i++)
#pragma unroll
            for (int j = 0; j < 4; j++) acc[i][j] = 0.f;

        const int kbase = kg * 128;
#pragma unroll 8
        for (int kk = 0; kk < 128; kk++) {
            int k = kbase + kk;
            float4 hb = *(const float4*)&h_sh[k * 32 + bx * 4];
            float4 wr = *(const float4*)&w_sh[k * 32 + rx * 4];
            acc[0][0] += hb.x * wr.x; acc[0][1] += hb.x * wr.y;
            acc[0][2] += hb.x * wr.z; acc[0][3] += hb.x * wr.w;
            acc[1][0] += hb.y * wr.x; acc[1][1] += hb.y * wr.y;
            acc[1][2] += hb.y * wr.z; acc[1][3] += hb.y * wr.w;
            acc[2][0] += hb.z * wr.x; acc[2][1] += hb.z * wr.y;
            acc[2][2] += hb.z * wr.z; acc[2][3] += hb.z * wr.w;
            acc[3][0] += hb.w * wr.x; acc[3][1] += hb.w * wr.y;
            acc[3][2] += hb.w * wr.z; acc[3][3] += hb.w * wr.w;
        }
#pragma unroll
        for (int i = 0; i < 4; i++) {
            float4 v = make_float4(acc[i][0], acc[i][1], acc[i][2], acc[i][3]);
            *(float4*)&part[kg * 1024 + (bx * 4 + i) * 32 + rx * 4] = v;
        }
        __syncthreads();

        // Epilogue: one (batch, col) per thread. Reduce 4 k-partials, add
        // x_proj, apply gates, update c, produce h.
        {
            const float* xpp = g_xp + ((size_t)t * NBATCH + (bbase + b_ep)) * G4H
                               + colbase + c_ep;
            float s[4];
#pragma unroll
            for (int g = 0; g < 4; g++) {
                int r = g * 8 + c_ep;
                float v = part[b_ep * 32 + r] + part[1024 + b_ep * 32 + r]
                        + part[2048 + b_ep * 32 + r] + part[3072 + b_ep * 32 + r];
                s[g] = v + xpp[(size_t)g * HDIM];
            }
            float iv = 1.f / (1.f + expf(-s[0]));
            float fv = 1.f / (1.f + expf(-s[1]));
            float gv = tanhf(s[2]);
            float ov = 1.f / (1.f + expf(-s[3]));
            float cn = fv * c_sh[b_ep * 8 + c_ep] + iv * gv;
            c_sh[b_ep * 8 + c_ep] = cn;
            float hn = ov * tanhf(cn);
            g_hbuf[cur ^ 1][(colbase + c_ep) * NBATCH + bbase + b_ep] = hn;
            out[((size_t)t * NBATCH + bbase + b_ep) * HDIM + colbase + c_ep] = hn;
        }
        grid_barrier();
    }
}

// ---------------------------------------------------------------------------
extern "C" void kernel_launch(void* const* d_in, const int* in_sizes, int n_in,
                              void* d_out, int out_size) {
    const float* x   = (const float*)d_in[0];
    const float* Wih = (const float*)d_in[1];
    const float* Whh = (const float*)d_in[2];
    const float* bih = (const float*)d_in[3];
    const float* bhh = (const float*)d_in[4];
    float* out = (float*)d_out;

    cudaFuncSetAttribute((const void*)lstm_rec,
                         cudaFuncAttributeMaxDynamicSharedMemorySize, 148480);

    dim3 g1(G4H / BN, (T_STEPS * NBATCH) / BM);   // (16, 256)
    xproj_gemm<<<g1, 256>>>(x, Wih, bih, bhh);
    lstm_rec<<<dim3(64, 2), 256, 148480>>>(Whh, out);
}

// round 10
// speedup vs baseline: 1.1465x; 1.1465x over previous
#include <cuda_runtime.h>
#include <cuda_bf16.h>
#include <cstdint>

#define T_STEPS 512
#define NBATCH  64
#define IDIM    512
#define HDIM    512
#define G4H     2048
#define NBLOCKS 128

// ---------------- device scratch (allocation-free rule) ----------------
__device__ float         g_xp[(size_t)T_STEPS * NBATCH * G4H];  // [T*B, 4H]
__device__ float         g_hbuf[2][HDIM * NBATCH];              // ping-pong h [h][b]
__device__ unsigned      g_count;
__device__ unsigned      g_gen;
__device__ __nv_bfloat16 g_Ahi[(size_t)T_STEPS * NBATCH * IDIM];
__device__ __nv_bfloat16 g_Alo[(size_t)T_STEPS * NBATCH * IDIM];
__device__ __nv_bfloat16 g_Bhi[(size_t)G4H * IDIM];
__device__ __nv_bfloat16 g_Blo[(size_t)G4H * IDIM];

// ---------------- portable PTX helpers (valid on plain sm_103) ----------------
__device__ __forceinline__ uint32_t smem_u32(const void* p) {
    uint32_t a;
    asm("{ .reg .u64 t; cvta.to.shared.u64 t, %1; cvt.u32.u64 %0, t; }" : "=r"(a) : "l"(p));
    return a;
}
#define CP_ASYNC16(dst, src) \
    asm volatile("cp.async.cg.shared.global [%0], [%1], 16;" :: "r"(dst), "l"(src))
#define CP_COMMIT() asm volatile("cp.async.commit_group;" ::: "memory")
#define CP_WAIT(n)  asm volatile("cp.async.wait_group %0;" :: "n"(n) : "memory")
#define LDSM_X4(r0, r1, r2, r3, addr)                                        \
    asm volatile("ldmatrix.sync.aligned.m8n8.x4.shared.b16 {%0,%1,%2,%3}, [%4];" \
                 : "=r"(r0), "=r"(r1), "=r"(r2), "=r"(r3) : "r"(addr))
#define MMA_BF16(c, a, b)                                                    \
    asm volatile("mma.sync.aligned.m16n8k16.row.col.f32.bf16.bf16.f32 "      \
                 "{%0,%1,%2,%3},{%4,%5,%6,%7},{%8,%9},{%0,%1,%2,%3};"        \
                 : "+f"((c)[0]), "+f"((c)[1]), "+f"((c)[2]), "+f"((c)[3])    \
                 : "r"((a)[0]), "r"((a)[1]), "r"((a)[2]), "r"((a)[3]),       \
                   "r"((b)[0]), "r"((b)[1]))

// ---------------------------------------------------------------------------
// Split fp32 -> (hi, lo) bf16 pair
// ---------------------------------------------------------------------------
__global__ void split_bf16(const float* __restrict__ src, __nv_bfloat16* __restrict__ hi,
                           __nv_bfloat16* __restrict__ lo, int n) {
    int i = blockIdx.x * blockDim.x + threadIdx.x;
    if (i < n) {
        float v = src[i];
        __nv_bfloat16 h = __float2bfloat16(v);
        hi[i] = h;
        lo[i] = __float2bfloat16(v - __bfloat162float(h));
    }
}

// ---------------------------------------------------------------------------
// HMMA split-bf16 GEMM: g_xp[M=32768, N=2048] = A @ B^T + bias
// 128x128 block tile, Kc=32, 2-stage cp.async pipeline, 8 warps (4 m x 2 n),
// warp tile 32x64 = 2x8 m16n8k16 atoms, 3 mma products per atom.
// SMEM tile rows padded to 40 bf16 (80 B) — 16B-aligned for ldmatrix.
// Stage layout (bytes): Ahi[0,10240) Alo[10240,20480) Bhi[20480,30720) Blo[30720,40960)
// Stages at 0 / 40960; bias float[128] at 81920. Total 82432.
// ---------------------------------------------------------------------------
#define XSTG 40960
#define TROW 80

__device__ __forceinline__ void xp_load_stage(uint32_t smb, int stage, int kc,
                                              int my, int nx, int tid) {
    const uint32_t sb = smb + stage * XSTG;
#pragma unroll
    for (int t = 0; t < 8; t++) {
        int i = tid + t * 256;          // 0..2047
        int tile = i >> 9;              // 0 Ahi, 1 Alo, 2 Bhi, 3 Blo
        int idx  = i & 511;
        int row  = idx >> 2;            // 0..127
        int q    = idx & 3;             // 16B quad within 64B row-chunk
        const __nv_bfloat16* src;
        int grow;
        if (tile == 0)      { src = g_Ahi; grow = my * 128 + row; }
        else if (tile == 1) { src = g_Alo; grow = my * 128 + row; }
        else if (tile == 2) { src = g_Bhi; grow = nx * 128 + row; }
        else                { src = g_Blo; grow = nx * 128 + row; }
        uint32_t dst = sb + tile * 10240 + row * TROW + q * 16;
        CP_ASYNC16(dst, src + (size_t)grow * IDIM + kc * 32 + q * 8);
    }
}

__global__ __launch_bounds__(256, 1)
void xproj_hmma(const float* __restrict__ bih, const float* __restrict__ bhh) {
    extern __shared__ char sm[];
    const uint32_t smb = smem_u32(sm);
    const int tid  = threadIdx.x;
    const int lane = tid & 31;
    const int wid  = tid >> 5;
    const int nx = blockIdx.x, my = blockIdx.y;
    const int warp_m = wid & 3, warp_n = wid >> 2;
    const int m_base = warp_m * 32, n_base = warp_n * 64;
    float* b_sh = (float*)(sm + 81920);

    if (tid < 128) b_sh[tid] = bih[nx * 128 + tid] + bhh[nx * 128 + tid];

    // per-lane ldmatrix byte offsets within a tile
    const uint32_t a_off = (uint32_t)(m_base + (lane & 15)) * TROW + (lane >> 4) * 16;
    const uint32_t b_off = (uint32_t)(n_base + (lane & 7) + ((lane >> 4) & 1) * 8) * TROW
                         + ((lane >> 3) & 1) * 16;

    float acc[2][8][4];
#pragma unroll
    for (int am = 0; am < 2; am++)
#pragma unroll
        for (int an = 0; an < 8; an++)
#pragma unroll
            for (int j = 0; j < 4; j++) acc[am][an][j] = 0.f;

    xp_load_stage(smb, 0, 0, my, nx, tid);
    CP_COMMIT();

    for (int c = 0; c < 16; c++) {
        if (c + 1 < 16) {
            xp_load_stage(smb, (c + 1) & 1, c + 1, my, nx, tid);
            CP_COMMIT();
            CP_WAIT(1);
        } else {
            CP_WAIT(0);
        }
        __syncthreads();

        const uint32_t sb = smb + (c & 1) * XSTG;
        const uint32_t aHi = sb + a_off;
        const uint32_t aLo = aHi + 10240;
        const uint32_t bHi = sb + 20480 + b_off;
        const uint32_t bLo = bHi + 10240;
#pragma unroll
        for (int ks = 0; ks < 2; ks++) {
            uint32_t ah[2][4], al[2][4], bh[8][2], bl[8][2];
            LDSM_X4(ah[0][0], ah[0][1], ah[0][2], ah[0][3], aHi + ks * 32);
            LDSM_X4(ah[1][0], ah[1][1], ah[1][2], ah[1][3], aHi + 1280 + ks * 32);
            LDSM_X4(al[0][0], al[0][1], al[0][2], al[0][3], aLo + ks * 32);
            LDSM_X4(al[1][0], al[1][1], al[1][2], al[1][3], aLo + 1280 + ks * 32);
#pragma unroll
            for (int p = 0; p < 4; p++) {
                LDSM_X4(bh[2*p][0], bh[2*p][1], bh[2*p+1][0], bh[2*p+1][1],
                        bHi + p * 1280 + ks * 32);
                LDSM_X4(bl[2*p][0], bl[2*p][1], bl[2*p+1][0], bl[2*p+1][1],
                        bLo + p * 1280 + ks * 32);
            }
#pragma unroll
            for (int am = 0; am < 2; am++)
#pragma unroll
                for (int an = 0; an < 8; an++) {
                    MMA_BF16(acc[am][an], ah[am], bh[an]);
                    MMA_BF16(acc[am][an], ah[am], bl[an]);
                    MMA_BF16(acc[am][an], al[am], bh[an]);
                }
        }
        __syncthreads();
    }

    // Epilogue: direct STG with bias
    const int qr = lane >> 2, qc = (lane & 3) * 2;
#pragma unroll
    for (int am = 0; am < 2; am++) {
        const size_t r0 = (size_t)my * 128 + m_base + am * 16 + qr;
#pragma unroll
        for (int an = 0; an < 8; an++) {
            const int cb = n_base + an * 8 + qc;
            const float b0 = b_sh[cb], b1 = b_sh[cb + 1];
            const size_t col = (size_t)nx * 128 + cb;
            *(float2*)&g_xp[r0 * G4H + col] =
                make_float2(acc[am][an][0] + b0, acc[am][an][1] + b1);
            *(float2*)&g_xp[(r0 + 8) * G4H + col] =
                make_float2(acc[am][an][2] + b0, acc[am][an][3] + b1);
        }
    }
}

// ---------------------------------------------------------------------------
// Grid barrier (sense-reversing, resident grid)
// ---------------------------------------------------------------------------
__device__ __forceinline__ void grid_barrier() {
    __threadfence();
    __syncthreads();
    if (threadIdx.x == 0) {
        volatile unsigned* vgen = &g_gen;
        unsigned gen = *vgen;
        if (atomicAdd(&g_count, 1u) == NBLOCKS - 1u) {
            g_count = 0u;
            __threadfence();
            atomicAdd(&g_gen, 1u);
        } else {
            while (*vgen == gen) { __nanosleep(64); }
        }
    }
    __syncthreads();
}

// ---------------------------------------------------------------------------
// Persistent recurrence (proven R1 structure; c-state in register, xp prefetch)
// ---------------------------------------------------------------------------
#define COLS 8
#define BB   32

extern __shared__ float smem[];

__global__ __launch_bounds__(256, 1)
void lstm_rec(const float* __restrict__ Whh, float* __restrict__ out) {
    float* w_sh = smem;            // [512][32]
    float* h_sh = smem + 16384;    // [512][32]
    float* part = smem + 32768;    // [4][32][32]
    const int tid = threadIdx.x;
    const int colbase = blockIdx.x * COLS;
    const int bbase   = blockIdx.y * BB;

    for (int idx = tid; idx < 32 * 512; idx += 256) {
        int r = idx >> 9, k = idx & 511;
        int g = r >> 3, c = r & 7;
        w_sh[k * 32 + r] = Whh[((size_t)(g * HDIM + colbase + c)) * HDIM + k];
    }
    {
        int c = tid >> 5, b = tid & 31;
        g_hbuf[0][(colbase + c) * NBATCH + bbase + b] = 0.f;
    }
    grid_barrier();

    const int kg = tid >> 6;
    const int tt = tid & 63;
    const int bx = tt & 7;
    const int rx = tt >> 3;
    const int b_ep = tid >> 3;
    const int c_ep = tid & 7;
    float creg = 0.f;

    for (int t = 0; t < T_STEPS; t++) {
        const int cur = t & 1;
        float xp[4];
        {
            const float* xpp = g_xp + ((size_t)t * NBATCH + (bbase + b_ep)) * G4H
                               + colbase + c_ep;
#pragma unroll
            for (int g = 0; g < 4; g++) xp[g] = __ldg(xpp + (size_t)g * HDIM);
        }
        for (int q = tid; q < 4096; q += 256) {
            int k = q >> 3, b4 = q & 7;
            float4 v = __ldcg((const float4*)&g_hbuf[cur][k * NBATCH + bbase + b4 * 4]);
            ((float4*)h_sh)[q] = v;
        }
        __syncthreads();

        float acc[4][4];
#pragma unroll
        for (int i = 0; i < 4; i++)
#pragma unroll
            for (int j = 0; j < 4; j++) acc[i][j] = 0.f;

        const int kbase = kg * 128;
#pragma unroll 8
        for (int kk = 0; kk < 128; kk++) {
            int k = kbase + kk;
            float4 hb = *(const float4*)&h_sh[k * 32 + bx * 4];
            float4 wr = *(const float4*)&w_sh[k * 32 + rx * 4];
            acc[0][0] += hb.x * wr.x; acc[0][1] += hb.x * wr.y;
            acc[0][2] += hb.x * wr.z; acc[0][3] += hb.x * wr.w;
            acc[1][0] += hb.y * wr.x; acc[1][1] += hb.y * wr.y;
            acc[1][2] += hb.y * wr.z; acc[1][3] += hb.y * wr.w;
            acc[2][0] += hb.z * wr.x; acc[2][1] += hb.z * wr.y;
            acc[2][2] += hb.z * wr.z; acc[2][3] += hb.z * wr.w;
            acc[3][0] += hb.w * wr.x; acc[3][1] += hb.w * wr.y;
            acc[3][2] += hb.w * wr.z; acc[3][3] += hb.w * wr.w;
        }
#pragma unroll
        for (int i = 0; i < 4; i++) {
            float4 v = make_float4(acc[i][0], acc[i][1], acc[i][2], acc[i][3]);
            *(float4*)&part[kg * 1024 + (bx * 4 + i) * 32 + rx * 4] = v;
        }
        __syncthreads();

        {
            float s[4];
#pragma unroll
            for (int g = 0; g < 4; g++) {
                int r = g * 8 + c_ep;
                float v = part[b_ep * 32 + r] + part[1024 + b_ep * 32 + r]
                        + part[2048 + b_ep * 32 + r] + part[3072 + b_ep * 32 + r];
                s[g] = v + xp[g];
            }
            float iv = 1.f / (1.f + expf(-s[0]));
            float fv = 1.f / (1.f + expf(-s[1]));
            float gv = tanhf(s[2]);
            float ov = 1.f / (1.f + expf(-s[3]));
            creg = fv * creg + iv * gv;
            float hn = ov * tanhf(creg);
            g_hbuf[cur ^ 1][(colbase + c_ep) * NBATCH + bbase + b_ep] = hn;
            out[((size_t)t * NBATCH + bbase + b_ep) * HDIM + colbase + c_ep] = hn;
        }
        grid_barrier();
    }
}

// ---------------------------------------------------------------------------
extern "C" void kernel_launch(void* const* d_in, const int* in_sizes, int n_in,
                              void* d_out, int out_size) {
    const float* x   = (const float*)d_in[0];
    const float* Wih = (const float*)d_in[1];
    const float* Whh = (const float*)d_in[2];
    const float* bih = (const float*)d_in[3];
    const float* bhh = (const float*)d_in[4];
    float* out = (float*)d_out;

    cudaFuncSetAttribute((const void*)xproj_hmma,
                         cudaFuncAttributeMaxDynamicSharedMemorySize, 82944);
    cudaFuncSetAttribute((const void*)lstm_rec,
                         cudaFuncAttributeMaxDynamicSharedMemorySize, 147456);

    __nv_bfloat16 *ahi, *alo, *bhi, *blo;
    cudaGetSymbolAddress((void**)&ahi, g_Ahi);
    cudaGetSymbolAddress((void**)&alo, g_Alo);
    cudaGetSymbolAddress((void**)&bhi, g_Bhi);
    cudaGetSymbolAddress((void**)&blo, g_Blo);

    const int nA = T_STEPS * NBATCH * IDIM;   // 16.8M
    const int nB = G4H * IDIM;                // 1M
    split_bf16<<<(nA + 255) / 256, 256>>>(x, ahi, alo, nA);
    split_bf16<<<(nB + 255) / 256, 256>>>(Wih, bhi, blo, nB);

    xproj_hmma<<<dim3(G4H / 128, (T_STEPS * NBATCH) / 128), 256, 82944>>>(bih, bhh);
    lstm_rec<<<dim3(64, 2), 256, 147456>>>(Whh, out);
}